// round 17
// baseline (speedup 1.0000x reference)
#include <cuda_runtime.h>

// 4D transposed conv, stride 2:
//   out[b,co,o1..o4] = bias[co] + sum_{ci,k1..k4 : o=2i+k} x[b,ci,i1..i4] * w[ci,co,k1..k4]
// Per (b,o1,o2) block, per valid (k1,k2)->(i1,i2) combo:
//   GEMM C[(i3,i4),(co,k3,k4)] = sum_ci x[ci,i3,i4]*w[ci,co,k3,k4]  (fma.rn.f32x2)
//   scatter out_s[co][2*i3+k3][2*i4+k4] += C
// 24 warps: warp (i3, ih) = i3 row x i4-half (6 i4 = 3 FFMA2 pairs); lane -> co.
// Accs = 27 u64 -> fits 84-reg cap at 768 threads (2x warp count vs R5).
// o4=12 seam crosses ih-halves (i4=5,k4=2 hi-write of ih0 vs i4=6,k4=0
// lo-write of ih1): ih1 stages its seam value in smem, round C (post-barrier)
// folds staged values in, write-disjoint. Round C strided over 800 cells
// (768 threads -> 2 trips for rows beyond 23; R14 bug was `if (tid<800)`).

#define NKW (81 * 64 * 64)
__device__ float g_wT[NKW];  // [k1,k2,k3,k4][ci][co]

__global__ void transpose_w_kernel(const float* __restrict__ w) {
    int idx = blockIdx.x * blockDim.x + threadIdx.x;
    if (idx < NKW) {
        int kidx = idx >> 12;        // 0..80
        int cico = idx & 4095;       // ci*64+co
        g_wT[idx] = w[cico * 81 + kidx];
    }
}

// smem (floats): out_s[32*625]=20000, w_s[9*64*32]=18432,
//                x_s[64*144]=9216, stage[12*3*32]=1152
#define WS_OFF  20000
#define XS_OFF  38432
#define STG_OFF 47648
#define SMEM_FLOATS 48800

typedef unsigned long long u64;

__device__ __forceinline__ void fma2(u64& d, u64 a, u64 b) {
    asm("fma.rn.f32x2 %0, %1, %2, %0;" : "+l"(d) : "l"(a), "l"(b));
}
__device__ __forceinline__ u64 pack2(float w) {
    u64 r;
    asm("mov.b64 %0, {%1, %1};" : "=l"(r) : "f"(w));
    return r;
}
__device__ __forceinline__ void unpack2(u64 v, float& lo, float& hi) {
    unsigned int l, h;
    asm("mov.b64 {%0, %1}, %2;" : "=r"(l), "=r"(h) : "l"(v));
    lo = __uint_as_float(l);
    hi = __uint_as_float(h);
}

__global__ __launch_bounds__(768, 1) void deconv4d_kernel(
    const float* __restrict__ x, const float* __restrict__ bias,
    float* __restrict__ out)
{
    extern __shared__ float smem[];
    float* out_s = smem;               // [32 co][25 o3][25 o4]
    float* w_s   = smem + WS_OFF;      // [t9=k3*3+k4][ci][co(32)]
    float* x_s   = smem + XS_OFF;      // [ci][i3*12+i4]
    float* stg   = smem + STG_OFF;     // [12 i3][3 k3][32 co] seam staging

    const int tid  = threadIdx.x;
    const int lane = tid & 31;         // -> co within half
    const int w24  = tid >> 5;         // 0..23
    const int i3   = w24 >> 1;         // warp's i3 row (0..11)
    const int ih   = w24 & 1;          // i4 half: i4 in [6*ih, 6*ih+5]
    const int i40  = ih * 6;
    const int b  = blockIdx.y;
    const int o1 = blockIdx.x / 25;
    const int o2 = blockIdx.x % 25;

    // valid (k,i) pairs for dims 1 and 2
    int nk1 = 0, k1s[2], i1s[2];
    #pragma unroll
    for (int k = 0; k < 3; k++)
        if (k <= o1 && ((o1 - k) & 1) == 0 && ((o1 - k) >> 1) < 12) {
            k1s[nk1] = k; i1s[nk1] = (o1 - k) >> 1; nk1++;
        }
    int nk2 = 0, k2s[2], i2s[2];
    #pragma unroll
    for (int k = 0; k < 3; k++)
        if (k <= o2 && ((o2 - k) & 1) == 0 && ((o2 - k) >> 1) < 12) {
            k2s[nk2] = k; i2s[nk2] = (o2 - k) >> 1; nk2++;
        }

    for (int coh = 0; coh < 2; coh++) {
        const int co0 = coh * 32;

        // init accumulation buffer with bias
        for (int i = tid; i < 20000; i += 768)
            out_s[i] = bias[co0 + i / 625];
        __syncthreads();

        for (int c1 = 0; c1 < nk1; c1++) {
            for (int c2 = 0; c2 < nk2; c2++) {
                const int i1 = i1s[c1], i2 = i2s[c2];
                const int kbase = (k1s[c1] * 3 + k2s[c2]) * 9;

                // x slab [64 ci][144] (contiguous per ci)
                for (int t = tid; t < 2304; t += 768) {
                    int ci = t / 36, r = t - ci * 36;
                    const float4* src = (const float4*)(x +
                        ((size_t)((b * 64 + ci) * 144 + i1 * 12 + i2)) * 144);
                    ((float4*)x_s)[t] = src[r];
                }
                // w slab [9 taps][64 ci][32 co]
                for (int t = tid; t < 4608; t += 768) {
                    int c4 = t & 7, ci = (t >> 3) & 63, t9 = t >> 9;
                    ((float4*)w_s)[t] = *(const float4*)(g_wT +
                        (kbase + t9) * 4096 + ci * 64 + co0 + c4 * 4);
                }
                __syncthreads();

                // mainloop: thread tile = 3 i4-pairs x 9 taps = 27 FFMA2 accs
                u64 acc[27];
                #pragma unroll
                for (int i = 0; i < 27; i++) acc[i] = 0ULL;

                const float* xb = x_s + i3 * 12 + i40;
                const float* wb = w_s + lane;
                for (int ci = 0; ci < 64; ci++) {
                    const u64* xp = (const u64*)(xb + ci * 144);  // 8B-aligned
                    u64 xv0 = xp[0], xv1 = xp[1], xv2 = xp[2];
                    const float* wr = wb + ci * 32;
                    #pragma unroll
                    for (int t9 = 0; t9 < 9; t9++) {
                        u64 w2 = pack2(wr[t9 * 2048]);
                        fma2(acc[t9 * 3 + 0], xv0, w2);
                        fma2(acc[t9 * 3 + 1], xv1, w2);
                        fma2(acc[t9 * 3 + 2], xv2, w2);
                    }
                }

                // ih=1: stage seam values (k4=0, p=0, lo half -> o4=12)
                if (ih) {
                    #pragma unroll
                    for (int k3 = 0; k3 < 3; k3++) {
                        float lo, hi;
                        unpack2(acc[9 * k3], lo, hi);   // t9=(k3,0), p=0
                        stg[i3 * 96 + k3 * 32 + lane] = lo;
                    }
                }

                float* osb = out_s + lane * 625;
                // Round A: k3 in {0,1} -> rows 2*i3+k3 (distinct across warps;
                // ih halves share rows but disjoint o4 after seam diversion)
                #pragma unroll
                for (int k3 = 0; k3 < 2; k3++) {
                    float* row = osb + (2 * i3 + k3) * 25 + 12 * ih;
                    #pragma unroll
                    for (int k4 = 0; k4 < 3; k4++) {
                        #pragma unroll
                        for (int p = 0; p < 3; p++) {
                            float lo, hi;
                            unpack2(acc[(k3 * 3 + k4) * 3 + p], lo, hi);
                            const int o4l = 4 * p + k4;  // +12*ih folded in row
                            if (!(ih && k4 == 0 && p == 0)) row[o4l] += lo;
                            row[o4l + 2] += hi;
                        }
                    }
                }
                __syncthreads();
                // Round B: k3 = 2 -> row 2*i3+2
                {
                    float* row = osb + (2 * i3 + 2) * 25 + 12 * ih;
                    #pragma unroll
                    for (int k4 = 0; k4 < 3; k4++) {
                        #pragma unroll
                        for (int p = 0; p < 3; p++) {
                            float lo, hi;
                            unpack2(acc[(6 + k4) * 3 + p], lo, hi);
                            const int o4l = 4 * p + k4;
                            if (!(ih && k4 == 0 && p == 0)) row[o4l] += lo;
                            row[o4l + 2] += hi;
                        }
                    }
                }
                __syncthreads();
                // Round C: fold staged seam values into (row, o4=12).
                // 800 cells, 768 threads -> strided (rows 24 on 2nd trip).
                // Each cell has 1-2 preimages (i3,k3): write-disjoint.
                for (int t = tid; t < 800; t += 768) {
                    const int r = t >> 5, co = t & 31;
                    float v = 0.0f;
                    if (r & 1) {
                        v = stg[((r - 1) >> 1) * 96 + 32 + co];        // k3=1
                    } else {
                        const int h = r >> 1;
                        if (h < 12) v = stg[h * 96 + co];              // k3=0
                        if (h >= 1) v += stg[(h - 1) * 96 + 64 + co];  // k3=2
                    }
                    out_s[co * 625 + r * 25 + 12] += v;
                }
                __syncthreads();  // scatter complete; safe to reload slabs
            }
        }

        // write this co-half (coalesced along o3*25+o4)
        for (int i = tid; i < 20000; i += 768) {
            int co = i / 625, r = i - co * 625;
            out[(size_t)(b * 64 + co0 + co) * 390625 +
                o1 * 15625 + o2 * 625 + r] = out_s[i];
        }
        __syncthreads();  // before re-init of out_s for next half
    }
}

extern "C" void kernel_launch(void* const* d_in, const int* in_sizes, int n_in,
                              void* d_out, int out_size) {
    const float* x    = (const float*)d_in[0];
    const float* w    = (const float*)d_in[1];
    const float* bias = (const float*)d_in[2];
    float* out = (float*)d_out;

    (void)in_sizes; (void)n_in; (void)out_size;

    // idempotent, deterministic; required for >48KB dynamic smem
    cudaFuncSetAttribute(deconv4d_kernel,
                         cudaFuncAttributeMaxDynamicSharedMemorySize,
                         SMEM_FLOATS * sizeof(float));

    transpose_w_kernel<<<(NKW + 255) / 256, 256>>>(w);

    dim3 grid(625, 4);
    deconv4d_kernel<<<grid, 768, SMEM_FLOATS * sizeof(float)>>>(x, bias, out);
}